// round 15
// baseline (speedup 1.0000x reference)
#include <cuda_runtime.h>
#include <math_constants.h>

#define BB 64
#define CC 256
#define HWN 3136
#define NF4 784        // 3136 / 4
#define SS 64
#define KK 8
#define BC (BB*CC)

// scratch (device globals — no allocation allowed in kernel_launch)
__device__ float g_sum[BC];
__device__ float g_min[BC];
__device__ float g_max[BC];
__device__ float g_scale[BC];
__device__ float g_smin[BB];
__device__ float g_smax[BB];
__device__ float g_qs[BB];
__device__ float g_qz[BB];
__device__ unsigned g_cnt[BB];  // per-sample arrival counters (zero-init, reset each call)
__device__ unsigned g_ticket;   // global arrival counter (zero-init, reset each call)

// ---------------------------------------------------------------------------
// Pass 1 (fused): per-(b,c) sum/min/max over the 3136-elem HW plane, PLUS the
// entire SE MLP + per-sample range + quant params, all inside one kernel.
//
//  - each block reduces its row (front-batched float4 loads, MLP=4)
//  - the LAST-arriving block of each sample b (per-b ticket) computes:
//      pooled -> layer1(relu) -> layer2 -> hardsigmoid scale row,
//      per-sample min/max of scale*x  (scale>=0 => scale*min/max(x)),
//    overlapped with the remaining DRAM traffic of other blocks.
//  - the LAST block globally (ticket) computes the K=8 cluster EMA / s / z.
// ---------------------------------------------------------------------------
__global__ __launch_bounds__(256) void k_reduce_se(const float* __restrict__ x,
                                                   const float* __restrict__ w1,
                                                   const float* __restrict__ b1,
                                                   const float* __restrict__ w2,
                                                   const float* __restrict__ b2,
                                                   const float* __restrict__ act_range,
                                                   const int* __restrict__ cinfo) {
    const int row = blockIdx.x;                       // b*C + c
    const int b   = row >> 8;
    const int t   = threadIdx.x;
    const float4* __restrict__ p =
        reinterpret_cast<const float4*>(x) + (size_t)row * NF4;

    const bool tail = (t < 16);
    float4 v0 = p[t];
    float4 v1 = p[t + 256];
    float4 v2 = p[t + 512];
    float4 v3 = p[tail ? (768 + t) : t];              // L1-hit dup for non-tail

    float s  = (v0.x + v0.y) + (v0.z + v0.w)
             + (v1.x + v1.y) + (v1.z + v1.w)
             + (v2.x + v2.y) + (v2.z + v2.w);
    float mn = fminf(fminf(fminf(v0.x, v0.y), fminf(v0.z, v0.w)),
               fminf(fminf(fminf(v1.x, v1.y), fminf(v1.z, v1.w)),
                     fminf(fminf(v2.x, v2.y), fminf(v2.z, v2.w))));
    float mx = fmaxf(fmaxf(fmaxf(v0.x, v0.y), fmaxf(v0.z, v0.w)),
               fmaxf(fmaxf(fmaxf(v1.x, v1.y), fmaxf(v1.z, v1.w)),
                     fmaxf(fmaxf(v2.x, v2.y), fmaxf(v2.z, v2.w))));
    if (tail) {
        s  += (v3.x + v3.y) + (v3.z + v3.w);
        mn  = fminf(mn, fminf(fminf(v3.x, v3.y), fminf(v3.z, v3.w)));
        mx  = fmaxf(mx, fmaxf(fmaxf(v3.x, v3.y), fmaxf(v3.z, v3.w)));
    }

    #pragma unroll
    for (int o = 16; o; o >>= 1) {
        s  += __shfl_xor_sync(0xffffffffu, s, o);
        mn  = fminf(mn, __shfl_xor_sync(0xffffffffu, mn, o));
        mx  = fmaxf(mx, __shfl_xor_sync(0xffffffffu, mx, o));
    }
    __shared__ float ss[8], smn[8], smx[8];
    __shared__ bool  s_se, s_last;
    __shared__ float sh[SS];
    __shared__ float redA[BB], redB[BB];

    const int w = t >> 5, l = t & 31;
    if (l == 0) { ss[w] = s; smn[w] = mn; smx[w] = mx; }
    __syncthreads();

    if (t == 0) {
        float S = ss[0], MN = smn[0], MX = smx[0];
        #pragma unroll
        for (int i = 1; i < 8; i++) {
            S += ss[i]; MN = fminf(MN, smn[i]); MX = fmaxf(MX, smx[i]);
        }
        g_sum[row] = S;
        g_min[row] = MN;
        g_max[row] = MX;
        __threadfence();                              // publish row results
        unsigned old = atomicAdd(&g_cnt[b], 1u);
        s_se = (old == 255u);
        if (s_se) {
            g_cnt[b] = 0;                             // reset for next replay
            __threadfence();                          // acquire peers' rows
        }
    }
    __syncthreads();
    if (!s_se) return;

    // ===== SE path: this block is the last arrival for sample b =====
    // layer1: 64 hidden units x 4 partial threads (dot length 256 -> 4 x 64)
    {
        const int hs   = t >> 2;                      // hidden unit 0..63
        const int part = t & 3;                       // quarter 0..3
        const float* __restrict__ ps = g_sum + b * CC + part * 64;
        const float* __restrict__ wr = w1 + hs * CC + part * 64;
        float acc = 0.0f;
        #pragma unroll
        for (int i = 0; i < 64; i++) acc = fmaf(ps[i], wr[i], acc);
        acc += __shfl_xor_sync(0xffffffffu, acc, 1);
        acc += __shfl_xor_sync(0xffffffffu, acc, 2);
        if (part == 0)
            sh[hs] = fmaxf(fmaf(acc, 1.0f / (float)HWN, b1[hs]), 0.0f);
    }
    __syncthreads();

    // layer2: one output channel per thread (dot length 64)
    float acc = b2[t];
    {
        const float* __restrict__ wr = w2 + t * SS;
        #pragma unroll
        for (int i = 0; i < SS; i++) acc = fmaf(sh[i], wr[i], acc);
    }
    float sc = fminf(fmaxf(acc * (1.0f / 6.0f) + 0.5f, 0.0f), 1.0f);   // hardsigmoid
    g_scale[b * CC + t] = sc;

    float vmn = sc * g_min[b * CC + t];
    float vmx = sc * g_max[b * CC + t];
    #pragma unroll
    for (int o = 16; o; o >>= 1) {
        vmn = fminf(vmn, __shfl_xor_sync(0xffffffffu, vmn, o));
        vmx = fmaxf(vmx, __shfl_xor_sync(0xffffffffu, vmx, o));
    }
    if (l == 0) { smn[w] = vmn; smx[w] = vmx; }
    __syncthreads();

    if (t == 0) {
        float MN = smn[0], MX = smx[0];
        #pragma unroll
        for (int i = 1; i < 8; i++) { MN = fminf(MN, smn[i]); MX = fmaxf(MX, smx[i]); }
        g_smin[b] = MN;
        g_smax[b] = MX;
        __threadfence();                              // publish before global ticket
        unsigned old = atomicAdd(&g_ticket, 1u);
        s_last = (old == (unsigned)(BB - 1));
        if (s_last) {
            g_ticket = 0;                             // reset for next replay
            __threadfence();                          // acquire all samples
        }
    }
    __syncthreads();
    if (!s_last) return;

    // ===== final tail: cluster EMA + quant params (parallel load, tiny math) =====
    if (t < BB) { redA[t] = g_smin[t]; redB[t] = g_smax[t]; }
    __syncthreads();

    if (t == 0) {
        int map[BB];
        int idx = 0;
        for (int k = 0; k < KK; k++) {
            int id  = cinfo[2 * k];
            int cnt = cinfo[2 * k + 1];
            for (int j = 0; j < cnt && idx < BB; j++) map[idx++] = id;
        }
        int lastid = (idx > 0) ? map[idx - 1] : 0;
        while (idx < BB) map[idx++] = lastid;

        float segmn[KK], segmx[KK];
        #pragma unroll
        for (int k = 0; k < KK; k++) { segmn[k] = CUDART_INF_F; segmx[k] = -CUDART_INF_F; }
        for (int bb = 0; bb < BB; bb++) {
            int k = map[bb];
            segmn[k] = fminf(segmn[k], redA[bb]);
            segmx[k] = fmaxf(segmx[k], redB[bb]);
        }
        float qs[KK], qz[KK];
        #pragma unroll
        for (int k = 0; k < KK; k++) {
            float nmn = act_range[2 * k]     * 0.995f + segmn[k] * 0.005f;
            float nmx = act_range[2 * k + 1] * 0.995f + segmx[k] * 0.005f;
            float sv  = fmaxf((nmx - nmn) / 15.0f, 1e-8f);
            qs[k] = sv;
            qz[k] = -rintf(nmn / sv);
        }
        for (int bb = 0; bb < BB; bb++) {
            g_qs[bb] = qs[map[bb]];
            g_qz[bb] = qz[map[bb]];
        }
        __threadfence();
    }
}

// ---------------------------------------------------------------------------
// Pass 2: elementwise fake quantize: out = (clip(rint(x*(sc/s) + z),0,15)-z)*s
// Reverse row order for L2 reuse of the tail of x left by pass 1; streaming
// (evict-first) loads and stores; front-batched full unroll (MLP=4);
// per-row precomputed a = sc/s turns mul+div+add into one fmaf per element.
// ---------------------------------------------------------------------------
__device__ __forceinline__ float fq(float v, float a, float s, float z) {
    float q = rintf(fmaf(v, a, z));
    q = fminf(fmaxf(q, 0.0f), 15.0f);
    return (q - z) * s;
}

__global__ __launch_bounds__(256) void k_quant(const float* __restrict__ x,
                                               float* __restrict__ out) {
    const int row = (BC - 1) - blockIdx.x;            // reverse order for L2 reuse
    const int b   = row >> 8;
    const int t   = threadIdx.x;
    const float sc = g_scale[row];
    const float s  = g_qs[b];
    const float z  = g_qz[b];
    const float a  = sc / s;

    const float4* __restrict__ p = reinterpret_cast<const float4*>(x)   + (size_t)row * NF4;
    float4*       __restrict__ o = reinterpret_cast<float4*>(out)       + (size_t)row * NF4;

    const bool tail = (t < 16);
    float4 v0 = __ldcs(&p[t]);
    float4 v1 = __ldcs(&p[t + 256]);
    float4 v2 = __ldcs(&p[t + 512]);
    float4 v3 = __ldcs(&p[tail ? (768 + t) : t]);

    float4 r0, r1, r2, r3;
    r0.x = fq(v0.x, a, s, z); r0.y = fq(v0.y, a, s, z);
    r0.z = fq(v0.z, a, s, z); r0.w = fq(v0.w, a, s, z);
    r1.x = fq(v1.x, a, s, z); r1.y = fq(v1.y, a, s, z);
    r1.z = fq(v1.z, a, s, z); r1.w = fq(v1.w, a, s, z);
    r2.x = fq(v2.x, a, s, z); r2.y = fq(v2.y, a, s, z);
    r2.z = fq(v2.z, a, s, z); r2.w = fq(v2.w, a, s, z);
    r3.x = fq(v3.x, a, s, z); r3.y = fq(v3.y, a, s, z);
    r3.z = fq(v3.z, a, s, z); r3.w = fq(v3.w, a, s, z);

    __stcs(&o[t],       r0);
    __stcs(&o[t + 256], r1);
    __stcs(&o[t + 512], r2);
    if (tail) __stcs(&o[768 + t], r3);
}

// ---------------------------------------------------------------------------
extern "C" void kernel_launch(void* const* d_in, const int* in_sizes, int n_in,
                              void* d_out, int out_size) {
    const float* x   = (const float*)d_in[0];
    const float* w1  = (const float*)d_in[1];
    const float* b1  = (const float*)d_in[2];
    const float* w2  = (const float*)d_in[3];
    const float* b2  = (const float*)d_in[4];
    const float* ar  = (const float*)d_in[5];
    const int*   ci  = (const int*)d_in[6];
    float*       out = (float*)d_out;

    k_reduce_se<<<BC, 256>>>(x, w1, b1, w2, b2, ar, ci);
    k_quant<<<BC, 256>>>(x, out);
}

// round 16
// speedup vs baseline: 1.9502x; 1.9502x over previous
#include <cuda_runtime.h>
#include <math_constants.h>

#define BB 64
#define CC 256
#define HWN 3136
#define NF4 784        // 3136 / 4
#define SS 64
#define KK 8
#define BC (BB*CC)

// scratch (device globals — no allocation allowed in kernel_launch)
__device__ float g_sum[BC];
__device__ float g_min[BC];
__device__ float g_max[BC];
__device__ float g_scale[BC];
__device__ float g_smin[BB];
__device__ float g_smax[BB];
__device__ float g_qs[BB];
__device__ float g_qz[BB];
__device__ unsigned g_ticket;   // zero-initialized; reset by last block each call

// ---------------------------------------------------------------------------
// Pass 1: per-(b,c) sum / min / max over the 3136-element HW plane.
// One block per (b,c) row. Front-batched float4 loads (MLP=4), full unroll.
// Measured at the LTS ceiling (79.6% DRAM, 6.3 TB/s) — do not touch.
// ---------------------------------------------------------------------------
__global__ __launch_bounds__(256) void k_reduce(const float* __restrict__ x) {
    const int row = blockIdx.x;                       // b*C + c
    const int t   = threadIdx.x;
    const float4* __restrict__ p =
        reinterpret_cast<const float4*>(x) + (size_t)row * NF4;

    const bool tail = (t < 16);
    float4 v0 = p[t];
    float4 v1 = p[t + 256];
    float4 v2 = p[t + 512];
    float4 v3 = p[tail ? (768 + t) : t];              // L1-hit dup for non-tail

    float s  = (v0.x + v0.y) + (v0.z + v0.w)
             + (v1.x + v1.y) + (v1.z + v1.w)
             + (v2.x + v2.y) + (v2.z + v2.w);
    float mn = fminf(fminf(fminf(v0.x, v0.y), fminf(v0.z, v0.w)),
               fminf(fminf(fminf(v1.x, v1.y), fminf(v1.z, v1.w)),
                     fminf(fminf(v2.x, v2.y), fminf(v2.z, v2.w))));
    float mx = fmaxf(fmaxf(fmaxf(v0.x, v0.y), fmaxf(v0.z, v0.w)),
               fmaxf(fmaxf(fmaxf(v1.x, v1.y), fmaxf(v1.z, v1.w)),
                     fmaxf(fmaxf(v2.x, v2.y), fmaxf(v2.z, v2.w))));
    if (tail) {
        s  += (v3.x + v3.y) + (v3.z + v3.w);
        mn  = fminf(mn, fminf(fminf(v3.x, v3.y), fminf(v3.z, v3.w)));
        mx  = fmaxf(mx, fmaxf(fmaxf(v3.x, v3.y), fmaxf(v3.z, v3.w)));
    }

    #pragma unroll
    for (int o = 16; o; o >>= 1) {
        s  += __shfl_xor_sync(0xffffffffu, s, o);
        mn  = fminf(mn, __shfl_xor_sync(0xffffffffu, mn, o));
        mx  = fmaxf(mx, __shfl_xor_sync(0xffffffffu, mx, o));
    }
    __shared__ float ss[8], smn[8], smx[8];
    const int w = t >> 5, l = t & 31;
    if (l == 0) { ss[w] = s; smn[w] = mn; smx[w] = mx; }
    __syncthreads();
    if (t == 0) {
        float S = ss[0], MN = smn[0], MX = smx[0];
        #pragma unroll
        for (int i = 1; i < 8; i++) {
            S += ss[i]; MN = fminf(MN, smn[i]); MX = fmaxf(MX, smx[i]);
        }
        g_sum[row] = S;
        g_min[row] = MN;
        g_max[row] = MX;
    }
}

// ---------------------------------------------------------------------------
// Pass 2: one block per sample b. SE MLP -> hardsigmoid scale; per-sample
// min/max of scale*x. Last block computes cluster EMA + quant params with
// PARALLEL smem staging (no serial thread-0 gmem loops).
// Weight loads are float4 (4x fewer L1tex wavefronts than scalar).
// ---------------------------------------------------------------------------
__global__ __launch_bounds__(256) void k_se(const float* __restrict__ w1,
                                            const float* __restrict__ b1,
                                            const float* __restrict__ w2,
                                            const float* __restrict__ b2,
                                            const float* __restrict__ act_range,
                                            const int* __restrict__ cinfo) {
    const int b = blockIdx.x;
    const int t = threadIdx.x;

    __shared__ float sp[CC];
    __shared__ float sh[SS];

    sp[t] = g_sum[b * CC + t];                        // raw sums; fold 1/HW later
    __syncthreads();

    // layer1: 4 threads per hidden unit, float4 weight loads over 64 floats each
    {
        const int hs   = t >> 2;                      // hidden unit 0..63
        const int part = t & 3;                       // quarter 0..3
        const float4* __restrict__ wr =
            reinterpret_cast<const float4*>(w1 + hs * CC + part * 64);
        const float* __restrict__ ps = sp + part * 64;
        float acc = 0.0f;
        #pragma unroll
        for (int i = 0; i < 16; i++) {
            float4 wv = wr[i];
            acc = fmaf(ps[4*i],   wv.x, acc);
            acc = fmaf(ps[4*i+1], wv.y, acc);
            acc = fmaf(ps[4*i+2], wv.z, acc);
            acc = fmaf(ps[4*i+3], wv.w, acc);
        }
        acc += __shfl_xor_sync(0xffffffffu, acc, 1);
        acc += __shfl_xor_sync(0xffffffffu, acc, 2);
        if (part == 0)
            sh[hs] = fmaxf(fmaf(acc, 1.0f / (float)HWN, b1[hs]), 0.0f);
    }
    __syncthreads();

    // layer2: one output channel per thread; float4 weight loads
    float acc = b2[t];
    {
        const float4* __restrict__ wr = reinterpret_cast<const float4*>(w2 + t * SS);
        #pragma unroll
        for (int i = 0; i < 16; i++) {
            float4 wv = wr[i];
            acc = fmaf(sh[4*i],   wv.x, acc);
            acc = fmaf(sh[4*i+1], wv.y, acc);
            acc = fmaf(sh[4*i+2], wv.z, acc);
            acc = fmaf(sh[4*i+3], wv.w, acc);
        }
    }
    float sc = fminf(fmaxf(acc * (1.0f / 6.0f) + 0.5f, 0.0f), 1.0f);   // hardsigmoid
    g_scale[b * CC + t] = sc;

    float vmn = sc * g_min[b * CC + t];   // scale >= 0 => min(scale*x) = scale*min(x)
    float vmx = sc * g_max[b * CC + t];
    #pragma unroll
    for (int o = 16; o; o >>= 1) {
        vmn = fminf(vmn, __shfl_xor_sync(0xffffffffu, vmn, o));
        vmx = fmaxf(vmx, __shfl_xor_sync(0xffffffffu, vmx, o));
    }
    __shared__ float rmn[8], rmx[8];
    __shared__ bool  s_last;
    const int w = t >> 5, l = t & 31;
    if (l == 0) { rmn[w] = vmn; rmx[w] = vmx; }
    __syncthreads();

    if (t == 0) {
        float MN = rmn[0], MX = rmx[0];
        #pragma unroll
        for (int i = 1; i < 8; i++) { MN = fminf(MN, rmn[i]); MX = fmaxf(MX, rmx[i]); }
        g_smin[b] = MN;
        g_smax[b] = MX;
        __threadfence();                               // publish before ticket (64 blocks only)
        unsigned old = atomicAdd(&g_ticket, 1u);
        s_last = (old == (unsigned)(BB - 1));
        if (s_last) {
            g_ticket = 0;                              // reset for next graph replay
            __threadfence();                           // acquire peers' g_smin/g_smax
        }
    }
    __syncthreads();
    if (!s_last) return;

    // ===== last block: cluster EMA + quant params, parallelized =====
    __shared__ float redMn[BB], redMx[BB];
    __shared__ int   s_id[KK];
    __shared__ int   s_off[KK + 1];
    __shared__ float s_qs[KK], s_qz[KK];               // per-segment-id (ids < K)

    if (t < BB) { redMn[t] = g_smin[t]; redMx[t] = g_smax[t]; }
    if (t < KK) s_id[t] = cinfo[2 * t];
    if (t == 0) {
        int off = 0;
        #pragma unroll
        for (int k = 0; k < KK; k++) {
            s_off[k] = (off < BB) ? off : BB;
            off += cinfo[2 * k + 1];
        }
        s_off[KK] = BB;                                // pad tail samples into last entry
    }
    __syncthreads();

    if (t < KK) {
        int lo = s_off[t], hi = s_off[t + 1];
        float mn = CUDART_INF_F, mx = -CUDART_INF_F;
        for (int i = lo; i < hi; i++) {
            mn = fminf(mn, redMn[i]);
            mx = fmaxf(mx, redMx[i]);
        }
        int id = s_id[t];
        float nmn = act_range[2 * id]     * 0.995f + mn * 0.005f;
        float nmx = act_range[2 * id + 1] * 0.995f + mx * 0.005f;
        float sv  = fmaxf((nmx - nmn) / 15.0f, 1e-8f);
        s_qs[t] = sv;                                  // per-entry (entries have unique ids here)
        s_qz[t] = -rintf(nmn / sv);
    }
    __syncthreads();

    if (t < BB) {
        int k = KK - 1;
        #pragma unroll
        for (int kk = KK - 1; kk >= 0; kk--)
            if (t < s_off[kk + 1] && t >= s_off[kk]) k = kk;
        if (t >= s_off[KK - 1]) k = KK - 1;            // padded tail -> last entry
        g_qs[t] = s_qs[k];
        g_qz[t] = s_qz[k];
    }
}

// ---------------------------------------------------------------------------
// Pass 3: elementwise fake quantize: out = (clip(rint(x*(sc/s) + z),0,15)-z)*s
// Reverse row order for L2 reuse of the tail of x left by pass 1; streaming
// loads/stores; front-batched full unroll (MLP=4); per-row a = sc/s -> 1 fmaf/elem.
// Measured 58.2us (7.0 TB/s effective) — keep as-is.
// ---------------------------------------------------------------------------
__device__ __forceinline__ float fq(float v, float a, float s, float z) {
    float q = rintf(fmaf(v, a, z));
    q = fminf(fmaxf(q, 0.0f), 15.0f);
    return (q - z) * s;
}

__global__ __launch_bounds__(256) void k_quant(const float* __restrict__ x,
                                               float* __restrict__ out) {
    const int row = (BC - 1) - blockIdx.x;            // reverse order for L2 reuse
    const int b   = row >> 8;
    const int t   = threadIdx.x;
    const float sc = g_scale[row];
    const float s  = g_qs[b];
    const float z  = g_qz[b];
    const float a  = sc / s;

    const float4* __restrict__ p = reinterpret_cast<const float4*>(x)   + (size_t)row * NF4;
    float4*       __restrict__ o = reinterpret_cast<float4*>(out)       + (size_t)row * NF4;

    const bool tail = (t < 16);
    float4 v0 = __ldcs(&p[t]);
    float4 v1 = __ldcs(&p[t + 256]);
    float4 v2 = __ldcs(&p[t + 512]);
    float4 v3 = __ldcs(&p[tail ? (768 + t) : t]);

    float4 r0, r1, r2, r3;
    r0.x = fq(v0.x, a, s, z); r0.y = fq(v0.y, a, s, z);
    r0.z = fq(v0.z, a, s, z); r0.w = fq(v0.w, a, s, z);
    r1.x = fq(v1.x, a, s, z); r1.y = fq(v1.y, a, s, z);
    r1.z = fq(v1.z, a, s, z); r1.w = fq(v1.w, a, s, z);
    r2.x = fq(v2.x, a, s, z); r2.y = fq(v2.y, a, s, z);
    r2.z = fq(v2.z, a, s, z); r2.w = fq(v2.w, a, s, z);
    r3.x = fq(v3.x, a, s, z); r3.y = fq(v3.y, a, s, z);
    r3.z = fq(v3.z, a, s, z); r3.w = fq(v3.w, a, s, z);

    __stcs(&o[t],       r0);
    __stcs(&o[t + 256], r1);
    __stcs(&o[t + 512], r2);
    if (tail) __stcs(&o[768 + t], r3);
}

// ---------------------------------------------------------------------------
extern "C" void kernel_launch(void* const* d_in, const int* in_sizes, int n_in,
                              void* d_out, int out_size) {
    const float* x   = (const float*)d_in[0];
    const float* w1  = (const float*)d_in[1];
    const float* b1  = (const float*)d_in[2];
    const float* w2  = (const float*)d_in[3];
    const float* b2  = (const float*)d_in[4];
    const float* ar  = (const float*)d_in[5];
    const int*   ci  = (const int*)d_in[6];
    float*       out = (float*)d_out;

    k_reduce<<<BC, 256>>>(x);
    k_se<<<BB, 256>>>(w1, b1, w2, b2, ar, ci);
    k_quant<<<BC, 256>>>(x, out);
}

// round 17
// speedup vs baseline: 1.9508x; 1.0003x over previous
#include <cuda_runtime.h>
#include <math_constants.h>

#define BB 64
#define CC 256
#define HWN 3136
#define NF4 784        // 3136 / 4
#define SS 64
#define KK 8
#define BC (BB*CC)

// scratch (device globals — no allocation allowed in kernel_launch)
__device__ float g_sum[BC];
__device__ float g_min[BC];
__device__ float g_max[BC];
__device__ float g_scale[BC];
__device__ float g_smin[BB];
__device__ float g_smax[BB];
__device__ float g_qs[BB];
__device__ float g_qz[BB];
__device__ unsigned g_ticket;   // zero-initialized; reset by last block each call

// ---------------------------------------------------------------------------
// Pass 1: per-(b,c) sum / min / max over the 3136-element HW plane.
// One block per (b,c) row. Front-batched float4 loads (MLP=4), full unroll.
// Measured at the LTS ceiling (79.6% DRAM, 6.3 TB/s) — do not touch.
// ---------------------------------------------------------------------------
__global__ __launch_bounds__(256) void k_reduce(const float* __restrict__ x) {
    const int row = blockIdx.x;                       // b*C + c
    const int t   = threadIdx.x;
    const float4* __restrict__ p =
        reinterpret_cast<const float4*>(x) + (size_t)row * NF4;

    const bool tail = (t < 16);
    float4 v0 = p[t];
    float4 v1 = p[t + 256];
    float4 v2 = p[t + 512];
    float4 v3 = p[tail ? (768 + t) : t];              // L1-hit dup for non-tail

    float s  = (v0.x + v0.y) + (v0.z + v0.w)
             + (v1.x + v1.y) + (v1.z + v1.w)
             + (v2.x + v2.y) + (v2.z + v2.w);
    float mn = fminf(fminf(fminf(v0.x, v0.y), fminf(v0.z, v0.w)),
               fminf(fminf(fminf(v1.x, v1.y), fminf(v1.z, v1.w)),
                     fminf(fminf(v2.x, v2.y), fminf(v2.z, v2.w))));
    float mx = fmaxf(fmaxf(fmaxf(v0.x, v0.y), fmaxf(v0.z, v0.w)),
               fmaxf(fmaxf(fmaxf(v1.x, v1.y), fmaxf(v1.z, v1.w)),
                     fmaxf(fmaxf(v2.x, v2.y), fmaxf(v2.z, v2.w))));
    if (tail) {
        s  += (v3.x + v3.y) + (v3.z + v3.w);
        mn  = fminf(mn, fminf(fminf(v3.x, v3.y), fminf(v3.z, v3.w)));
        mx  = fmaxf(mx, fmaxf(fmaxf(v3.x, v3.y), fmaxf(v3.z, v3.w)));
    }

    #pragma unroll
    for (int o = 16; o; o >>= 1) {
        s  += __shfl_xor_sync(0xffffffffu, s, o);
        mn  = fminf(mn, __shfl_xor_sync(0xffffffffu, mn, o));
        mx  = fmaxf(mx, __shfl_xor_sync(0xffffffffu, mx, o));
    }
    __shared__ float ss[8], smn[8], smx[8];
    const int w = t >> 5, l = t & 31;
    if (l == 0) { ss[w] = s; smn[w] = mn; smx[w] = mx; }
    __syncthreads();
    if (t == 0) {
        float S = ss[0], MN = smn[0], MX = smx[0];
        #pragma unroll
        for (int i = 1; i < 8; i++) {
            S += ss[i]; MN = fminf(MN, smn[i]); MX = fmaxf(MX, smx[i]);
        }
        g_sum[row] = S;
        g_min[row] = MN;
        g_max[row] = MX;
    }
}

// ---------------------------------------------------------------------------
// Pass 2: one block per sample b. SE MLP -> hardsigmoid scale; per-sample
// min/max of scale*x. Last block computes cluster EMA + quant params with
// PARALLEL smem staging (no serial thread-0 gmem loops).
// Weight loads are float4 (4x fewer L1tex wavefronts than scalar).
// ---------------------------------------------------------------------------
__global__ __launch_bounds__(256) void k_se(const float* __restrict__ w1,
                                            const float* __restrict__ b1,
                                            const float* __restrict__ w2,
                                            const float* __restrict__ b2,
                                            const float* __restrict__ act_range,
                                            const int* __restrict__ cinfo) {
    const int b = blockIdx.x;
    const int t = threadIdx.x;

    __shared__ float sp[CC];
    __shared__ float sh[SS];

    sp[t] = g_sum[b * CC + t];                        // raw sums; fold 1/HW later
    __syncthreads();

    // layer1: 4 threads per hidden unit, float4 weight loads over 64 floats each
    {
        const int hs   = t >> 2;                      // hidden unit 0..63
        const int part = t & 3;                       // quarter 0..3
        const float4* __restrict__ wr =
            reinterpret_cast<const float4*>(w1 + hs * CC + part * 64);
        const float* __restrict__ ps = sp + part * 64;
        float acc = 0.0f;
        #pragma unroll
        for (int i = 0; i < 16; i++) {
            float4 wv = wr[i];
            acc = fmaf(ps[4*i],   wv.x, acc);
            acc = fmaf(ps[4*i+1], wv.y, acc);
            acc = fmaf(ps[4*i+2], wv.z, acc);
            acc = fmaf(ps[4*i+3], wv.w, acc);
        }
        acc += __shfl_xor_sync(0xffffffffu, acc, 1);
        acc += __shfl_xor_sync(0xffffffffu, acc, 2);
        if (part == 0)
            sh[hs] = fmaxf(fmaf(acc, 1.0f / (float)HWN, b1[hs]), 0.0f);
    }
    __syncthreads();

    // layer2: one output channel per thread; float4 weight loads
    float acc = b2[t];
    {
        const float4* __restrict__ wr = reinterpret_cast<const float4*>(w2 + t * SS);
        #pragma unroll
        for (int i = 0; i < 16; i++) {
            float4 wv = wr[i];
            acc = fmaf(sh[4*i],   wv.x, acc);
            acc = fmaf(sh[4*i+1], wv.y, acc);
            acc = fmaf(sh[4*i+2], wv.z, acc);
            acc = fmaf(sh[4*i+3], wv.w, acc);
        }
    }
    float sc = fminf(fmaxf(acc * (1.0f / 6.0f) + 0.5f, 0.0f), 1.0f);   // hardsigmoid
    g_scale[b * CC + t] = sc;

    float vmn = sc * g_min[b * CC + t];   // scale >= 0 => min(scale*x) = scale*min(x)
    float vmx = sc * g_max[b * CC + t];
    #pragma unroll
    for (int o = 16; o; o >>= 1) {
        vmn = fminf(vmn, __shfl_xor_sync(0xffffffffu, vmn, o));
        vmx = fmaxf(vmx, __shfl_xor_sync(0xffffffffu, vmx, o));
    }
    __shared__ float rmn[8], rmx[8];
    __shared__ bool  s_last;
    const int w = t >> 5, l = t & 31;
    if (l == 0) { rmn[w] = vmn; rmx[w] = vmx; }
    __syncthreads();

    if (t == 0) {
        float MN = rmn[0], MX = rmx[0];
        #pragma unroll
        for (int i = 1; i < 8; i++) { MN = fminf(MN, rmn[i]); MX = fmaxf(MX, rmx[i]); }
        g_smin[b] = MN;
        g_smax[b] = MX;
        __threadfence();                               // publish before ticket (64 blocks only)
        unsigned old = atomicAdd(&g_ticket, 1u);
        s_last = (old == (unsigned)(BB - 1));
        if (s_last) {
            g_ticket = 0;                              // reset for next graph replay
            __threadfence();                           // acquire peers' g_smin/g_smax
        }
    }
    __syncthreads();
    if (!s_last) return;

    // ===== last block: cluster EMA + quant params, parallelized =====
    __shared__ float redMn[BB], redMx[BB];
    __shared__ int   s_id[KK];
    __shared__ int   s_off[KK + 1];
    __shared__ float s_qs[KK], s_qz[KK];               // per-segment-id (ids < K)

    if (t < BB) { redMn[t] = g_smin[t]; redMx[t] = g_smax[t]; }
    if (t < KK) s_id[t] = cinfo[2 * t];
    if (t == 0) {
        int off = 0;
        #pragma unroll
        for (int k = 0; k < KK; k++) {
            s_off[k] = (off < BB) ? off : BB;
            off += cinfo[2 * k + 1];
        }
        s_off[KK] = BB;                                // pad tail samples into last entry
    }
    __syncthreads();

    if (t < KK) {
        int lo = s_off[t], hi = s_off[t + 1];
        float mn = CUDART_INF_F, mx = -CUDART_INF_F;
        for (int i = lo; i < hi; i++) {
            mn = fminf(mn, redMn[i]);
            mx = fmaxf(mx, redMx[i]);
        }
        int id = s_id[t];
        float nmn = act_range[2 * id]     * 0.995f + mn * 0.005f;
        float nmx = act_range[2 * id + 1] * 0.995f + mx * 0.005f;
        float sv  = fmaxf((nmx - nmn) / 15.0f, 1e-8f);
        s_qs[t] = sv;                                  // per-entry (entries have unique ids here)
        s_qz[t] = -rintf(nmn / sv);
    }
    __syncthreads();

    if (t < BB) {
        int k = KK - 1;
        #pragma unroll
        for (int kk = KK - 1; kk >= 0; kk--)
            if (t < s_off[kk + 1] && t >= s_off[kk]) k = kk;
        if (t >= s_off[KK - 1]) k = KK - 1;            // padded tail -> last entry
        g_qs[t] = s_qs[k];
        g_qz[t] = s_qz[k];
    }
}

// ---------------------------------------------------------------------------
// Pass 3: elementwise fake quantize: out = (clip(rint(x*(sc/s) + z),0,15)-z)*s
// Reverse row order for L2 reuse of the tail of x left by pass 1; streaming
// loads/stores; front-batched full unroll (MLP=4); per-row a = sc/s -> 1 fmaf/elem.
// Measured 58.2us (7.0 TB/s effective) — keep as-is.
// ---------------------------------------------------------------------------
__device__ __forceinline__ float fq(float v, float a, float s, float z) {
    float q = rintf(fmaf(v, a, z));
    q = fminf(fmaxf(q, 0.0f), 15.0f);
    return (q - z) * s;
}

__global__ __launch_bounds__(256) void k_quant(const float* __restrict__ x,
                                               float* __restrict__ out) {
    const int row = (BC - 1) - blockIdx.x;            // reverse order for L2 reuse
    const int b   = row >> 8;
    const int t   = threadIdx.x;
    const float sc = g_scale[row];
    const float s  = g_qs[b];
    const float z  = g_qz[b];
    const float a  = sc / s;

    const float4* __restrict__ p = reinterpret_cast<const float4*>(x)   + (size_t)row * NF4;
    float4*       __restrict__ o = reinterpret_cast<float4*>(out)       + (size_t)row * NF4;

    const bool tail = (t < 16);
    float4 v0 = __ldcs(&p[t]);
    float4 v1 = __ldcs(&p[t + 256]);
    float4 v2 = __ldcs(&p[t + 512]);
    float4 v3 = __ldcs(&p[tail ? (768 + t) : t]);

    float4 r0, r1, r2, r3;
    r0.x = fq(v0.x, a, s, z); r0.y = fq(v0.y, a, s, z);
    r0.z = fq(v0.z, a, s, z); r0.w = fq(v0.w, a, s, z);
    r1.x = fq(v1.x, a, s, z); r1.y = fq(v1.y, a, s, z);
    r1.z = fq(v1.z, a, s, z); r1.w = fq(v1.w, a, s, z);
    r2.x = fq(v2.x, a, s, z); r2.y = fq(v2.y, a, s, z);
    r2.z = fq(v2.z, a, s, z); r2.w = fq(v2.w, a, s, z);
    r3.x = fq(v3.x, a, s, z); r3.y = fq(v3.y, a, s, z);
    r3.z = fq(v3.z, a, s, z); r3.w = fq(v3.w, a, s, z);

    __stcs(&o[t],       r0);
    __stcs(&o[t + 256], r1);
    __stcs(&o[t + 512], r2);
    if (tail) __stcs(&o[768 + t], r3);
}

// ---------------------------------------------------------------------------
extern "C" void kernel_launch(void* const* d_in, const int* in_sizes, int n_in,
                              void* d_out, int out_size) {
    const float* x   = (const float*)d_in[0];
    const float* w1  = (const float*)d_in[1];
    const float* b1  = (const float*)d_in[2];
    const float* w2  = (const float*)d_in[3];
    const float* b2  = (const float*)d_in[4];
    const float* ar  = (const float*)d_in[5];
    const int*   ci  = (const int*)d_in[6];
    float*       out = (float*)d_out;

    k_reduce<<<BC, 256>>>(x);
    k_se<<<BB, 256>>>(w1, b1, w2, b2, ar, ci);
    k_quant<<<BC, 256>>>(x, out);
}